// round 11
// baseline (speedup 1.0000x reference)
#include <cuda_runtime.h>
#include <cuda_fp16.h>

// ---------------- problem constants ----------------
#define NMAX 50000
#define EMAX 800000
#define MKER 27            // 3^3 spline kernels
#define C    64            // hidden channels
#define YSTR (MKER * C)    // 1728 halves per node
#define SSTR 108           // 27 * 4 (ci0,ci1,ci2,pad) layer-0 agg row
#define NBLK 4             // src blocks per node pass (43.2 MB y working set)

// ---------------- static scratch ----------------
__device__ __half g_y[(size_t)NMAX * YSTR];   // 172.8 MB transformed features (fp16)
__device__ float  g_root[NMAX * C];           // fp32 root-weight term h @ Wr
__device__ float  g_h[NMAX * C];              // hidden state (fp32)
__device__ float  g_agg[NMAX * C];            // fp32 cross-pass accumulator
__device__ float  g_S[NMAX * SSTR];           // layer-0 input-space agg (21.6 MB)
__device__ float4 g_rec[EMAX];                // CSR edge records: (src, ea0, ea1, ea2)
__device__ int    g_rowptr4[NBLK * NMAX + 1]; // per-(dst, srcblock) segment offsets
__device__ int    g_cursor4[NBLK * NMAX];
__device__ int    g_deg4[NBLK * NMAX];

// ---------------- helpers ----------------
__device__ __forceinline__ float2 ffma2(float2 a, float2 b, float2 c) {
    float2 d;
    asm("fma.rn.f32x2 %0, %1, %2, %3;"
        : "=l"(*reinterpret_cast<unsigned long long*>(&d))
        : "l"(*reinterpret_cast<unsigned long long*>(&a)),
          "l"(*reinterpret_cast<unsigned long long*>(&b)),
          "l"(*reinterpret_cast<unsigned long long*>(&c)));
    return d;
}

__device__ __forceinline__ void basis8(float e0, float e1, float e2,
                                       float w[8], int kk[8]) {
    float p0 = e0 * 2.0f, p1 = e1 * 2.0f, p2 = e2 * 2.0f;
    float f0 = fminf(fmaxf(floorf(p0), 0.f), 1.f);
    float f1 = fminf(fmaxf(floorf(p1), 0.f), 1.f);
    float f2 = fminf(fmaxf(floorf(p2), 0.f), 1.f);
    float u0 = p0 - f0, u1 = p1 - f1, u2 = p2 - f2;
    int base = (int)f0 + 3 * (int)f1 + 9 * (int)f2;
#pragma unroll
    for (int b = 0; b < 8; b++) {
        float a0 = (b & 1) ? u0 : 1.f - u0;
        float a1 = (b & 2) ? u1 : 1.f - u1;
        float a2 = (b & 4) ? u2 : 1.f - u2;
        w[b]  = a0 * a1 * a2;
        kk[b] = base + (b & 1) + 3 * ((b >> 1) & 1) + 9 * ((b >> 2) & 1);
    }
}

// ---------------- prepass ----------------
__global__ void zeroAll_kernel(int N) {
    int i = blockIdx.x * blockDim.x + threadIdx.x;
    if (i < N * SSTR) g_S[i] = 0.f;
    if (i < NBLK * N) g_deg4[i] = 0;
}
__global__ void hist_kernel(const int* __restrict__ src,
                            const int* __restrict__ dst, int E, int Nb) {
    int i = blockIdx.x * blockDim.x + threadIdx.x;
    if (i < E) {
        int b = min(src[i] / Nb, NBLK - 1);
        atomicAdd(&g_deg4[NBLK * dst[i] + b], 1);
    }
}
// single-block exclusive scan of g_deg4 (4N entries) -> g_rowptr4 / g_cursor4
__global__ void scan_kernel(int N4) {
    __shared__ int ssum[1024];
    int tid = threadIdx.x;
    int chunk = (N4 + 1023) / 1024;
    int beg = tid * chunk;
    int end = min(beg + chunk, N4);
    int s = 0;
    for (int i = beg; i < end; i++) s += g_deg4[i];
    ssum[tid] = s;
    __syncthreads();
    for (int off = 1; off < 1024; off <<= 1) {
        int v = 0;
        if (tid >= off) v = ssum[tid - off];
        __syncthreads();
        if (tid >= off) ssum[tid] += v;
        __syncthreads();
    }
    int run = (tid == 0) ? 0 : ssum[tid - 1];
    for (int i = beg; i < end; i++) {
        g_rowptr4[i] = run;
        g_cursor4[i] = run;
        run += g_deg4[i];
    }
    if (tid == 1023) g_rowptr4[N4] = ssum[1023];
}

// edge pass: write CSR record (dst, src-block bucketed) + layer-0 scatter
__global__ void build_kernel(const int* __restrict__ src,
                             const int* __restrict__ dst,
                             const float* __restrict__ ea,
                             const float* __restrict__ x, int E, int Nb) {
    int e = blockIdx.x * blockDim.x + threadIdx.x;
    if (e >= E) return;
    int s = src[e], d = dst[e];
    float e0 = ea[3 * e], e1 = ea[3 * e + 1], e2 = ea[3 * e + 2];

    int b   = min(s / Nb, NBLK - 1);
    int pos = atomicAdd(&g_cursor4[NBLK * d + b], 1);
    g_rec[pos] = make_float4(__int_as_float(s), e0, e1, e2);

    float w[8]; int kk[8];
    basis8(e0, e1, e2, w, kk);
    float x0 = __ldg(x + 3 * s), x1 = __ldg(x + 3 * s + 1), x2 = __ldg(x + 3 * s + 2);
    float4* Sb = (float4*)(g_S + (size_t)d * SSTR);
#pragma unroll
    for (int c = 0; c < 8; c++)
        atomicAdd(Sb + kk[c], make_float4(w[c] * x0, w[c] * x1, w[c] * x2, 0.f));
}

// ---------------- layer 0 finalize: h = relu(S@W0/deg + x@root0 + b0) --------
__global__ void __launch_bounds__(256)
l0_kernel(const float* __restrict__ x, const float* __restrict__ W0,
          const float* __restrict__ root0, const float* __restrict__ b0, int N) {
    int n    = (blockIdx.x * blockDim.x + threadIdx.x) >> 5;
    int lane = threadIdx.x & 31;
    if (n >= N) return;
    const float* Sr = g_S + (size_t)n * SSTR;
    float sA = Sr[lane];
    float sB = Sr[32 + lane];
    float sC = Sr[64 + lane];
    float sD = (lane < 12) ? Sr[96 + lane] : 0.f;

    float2 acc = make_float2(0.f, 0.f);
#pragma unroll
    for (int m = 0; m < MKER; m++) {
#pragma unroll
        for (int ci = 0; ci < 3; ci++) {
            int s  = m * 4 + ci;
            int r  = s >> 5, sl = s & 31;
            float v = (r == 0) ? __shfl_sync(0xffffffffu, sA, sl)
                    : (r == 1) ? __shfl_sync(0xffffffffu, sB, sl)
                    : (r == 2) ? __shfl_sync(0xffffffffu, sC, sl)
                               : __shfl_sync(0xffffffffu, sD, sl);
            float2 wv = __ldg((const float2*)(W0 + (m * 3 + ci) * C) + lane);
            acc.x += v * wv.x;
            acc.y += v * wv.y;
        }
    }
    int   dg  = g_rowptr4[NBLK * (n + 1)] - g_rowptr4[NBLK * n];
    float inv = 1.f / (float)(dg > 0 ? dg : 1);
    float xv  = (lane < 3) ? __ldg(x + 3 * n + lane) : 0.f;
    float x0  = __shfl_sync(0xffffffffu, xv, 0);
    float x1  = __shfl_sync(0xffffffffu, xv, 1);
    float x2  = __shfl_sync(0xffffffffu, xv, 2);
    float2 r0 = __ldg((const float2*)(root0)         + lane);
    float2 r1 = __ldg((const float2*)(root0 + C)     + lane);
    float2 r2 = __ldg((const float2*)(root0 + 2 * C) + lane);
    float2 bb = __ldg((const float2*)(b0)            + lane);
    float2 res;
    res.x = fmaxf(acc.x * inv + x0 * r0.x + x1 * r1.x + x2 * r2.x + bb.x, 0.f);
    res.y = fmaxf(acc.y * inv + x0 * r0.y + x1 * r1.y + x2 * r2.y + bb.y, 0.f);
    ((float2*)g_h)[(size_t)n * 32 + lane] = res;
}

// ---------------- transform (R10 conflict-free orientation, unchanged) -------
#define T_NODES 64
#define HT_STR  68
__global__ void __launch_bounds__(256)
transform_kernel(const float* __restrict__ h, const float* __restrict__ W,
                 const float* __restrict__ Wr, int N) {
    __shared__ float Wt[C * C];        // [ci][co] natural
    __shared__ float hsT[C * HT_STR];  // [ci][n] padded
    int m   = blockIdx.y;
    int n0  = blockIdx.x * T_NODES;
    int tid = threadIdx.x;

    const float* Wm = (m < MKER) ? (W + m * C * C) : Wr;
    for (int i = tid; i < C * C; i += 256)
        Wt[i] = Wm[i];
    for (int i = tid; i < T_NODES * C; i += 256) {
        int nl = i >> 6, ci = i & 63;
        int n  = n0 + nl;
        hsT[ci * HT_STR + nl] = (n < N) ? h[(size_t)n * C + ci] : 0.f;
    }
    __syncthreads();

    int co = tid & 63;
    int nb = (tid >> 6) * 16;

    float2 acc[8];
#pragma unroll
    for (int j = 0; j < 8; j++) acc[j] = make_float2(0.f, 0.f);

#pragma unroll 8
    for (int ci = 0; ci < C; ci++) {
        float  w  = Wt[ci * C + co];
        float2 wd = make_float2(w, w);
        const float4* hp = (const float4*)&hsT[ci * HT_STR + nb];
        float4 a = hp[0], b = hp[1], c = hp[2], d = hp[3];
        acc[0] = ffma2(make_float2(a.x, a.y), wd, acc[0]);
        acc[1] = ffma2(make_float2(a.z, a.w), wd, acc[1]);
        acc[2] = ffma2(make_float2(b.x, b.y), wd, acc[2]);
        acc[3] = ffma2(make_float2(b.z, b.w), wd, acc[3]);
        acc[4] = ffma2(make_float2(c.x, c.y), wd, acc[4]);
        acc[5] = ffma2(make_float2(c.z, c.w), wd, acc[5]);
        acc[6] = ffma2(make_float2(d.x, d.y), wd, acc[6]);
        acc[7] = ffma2(make_float2(d.z, d.w), wd, acc[7]);
    }

#pragma unroll
    for (int j = 0; j < 8; j++) {
        int n = n0 + nb + 2 * j;
        if (n >= N) break;
        if (m < MKER) {
            g_y[(size_t)n * YSTR + m * C + co] = __float2half_rn(acc[j].x);
            if (n + 1 < N)
                g_y[(size_t)(n + 1) * YSTR + m * C + co] = __float2half_rn(acc[j].y);
        } else {
            g_root[(size_t)n * C + co] = acc[j].x;
            if (n + 1 < N)
                g_root[(size_t)(n + 1) * C + co] = acc[j].y;
        }
    }
}

// ---------------- node pass (layers 1,2): warp per dst, one src-block -------
// Pass p touches only y rows of srcs in block p (43.2 MB -> L2-resident).
// Passes serialized by stream order; fp32 acc carried in g_agg; last pass
// fuses deg / root / bias / relu.
__global__ void __launch_bounds__(256)
node_pass_kernel(const float* __restrict__ bias, float* __restrict__ h_out,
                 int N, int p, int isLast) {
    __shared__ float4 recs[8][32];
    int wid  = threadIdx.x >> 5;
    int lane = threadIdx.x & 31;
    int n    = (blockIdx.x * blockDim.x + threadIdx.x) >> 5;
    if (n >= N) return;
    int beg = g_rowptr4[NBLK * n + p], end = g_rowptr4[NBLK * n + p + 1];

    float2 acc = (p == 0) ? make_float2(0.f, 0.f)
                          : ((float2*)g_agg)[(size_t)n * 32 + lane];

    for (int base = beg; base < end; base += 32) {
        int cnt = min(32, end - base);
        __syncwarp();
        if (lane < cnt) recs[wid][lane] = __ldg(&g_rec[base + lane]);
        __syncwarp();
#pragma unroll 4
        for (int e = 0; e < cnt; e++) {
            float4 r = recs[wid][e];                 // LDS broadcast
            int s = __float_as_int(r.x);
            float w[8]; int kk[8];
            basis8(r.y, r.z, r.w, w, kk);
            const __half* yb = g_y + (size_t)s * YSTR;
#pragma unroll
            for (int c = 0; c < 8; c++) {
                __half2 hv = __ldg((const __half2*)(yb + kk[c] * C) + lane);
                float2 v = __half22float2(hv);
                acc.x += w[c] * v.x;
                acc.y += w[c] * v.y;
            }
        }
    }

    if (!isLast) {
        ((float2*)g_agg)[(size_t)n * 32 + lane] = acc;
    } else {
        int   dg  = g_rowptr4[NBLK * (n + 1)] - g_rowptr4[NBLK * n];
        float inv = 1.f / (float)(dg > 0 ? dg : 1);
        float2 rt = __ldg((const float2*)(g_root + (size_t)n * C) + lane);
        float2 bb = __ldg((const float2*)bias + lane);
        float2 res;
        res.x = fmaxf(acc.x * inv + rt.x + bb.x, 0.f);
        res.y = fmaxf(acc.y * inv + rt.y + bb.y, 0.f);
        ((float2*)h_out)[(size_t)n * 32 + lane] = res;
    }
}

// ---------------- launch ----------------
extern "C" void kernel_launch(void* const* d_in, const int* in_sizes, int n_in,
                              void* d_out, int out_size) {
    const float* x     = (const float*)d_in[0];
    const int*   ei    = (const int*)d_in[1];
    const float* ea    = (const float*)d_in[2];
    const float* W0    = (const float*)d_in[3];
    const float* root0 = (const float*)d_in[4];
    const float* b0    = (const float*)d_in[5];
    const float* W1    = (const float*)d_in[6];
    const float* root1 = (const float*)d_in[7];
    const float* b1    = (const float*)d_in[8];
    const float* W2    = (const float*)d_in[9];
    const float* root2 = (const float*)d_in[10];
    const float* b2    = (const float*)d_in[11];
    float* out = (float*)d_out;

    int N = in_sizes[0] / 3;
    int E = in_sizes[1] / 2;
    const int* src = ei;
    const int* dst = ei + E;
    int Nb = (N + NBLK - 1) / NBLK;

    float* hP;
    cudaGetSymbolAddress((void**)&hP, g_h);

    int nodeBlocks = (N * 32 + 255) / 256;
    dim3 tGrid((N + T_NODES - 1) / T_NODES, MKER + 1);

    // ---- prepass: (dst, src-block) CSR + layer-0 scatter ----
    zeroAll_kernel<<<(N * SSTR + 255) / 256, 256>>>(N);
    hist_kernel<<<(E + 255) / 256, 256>>>(src, dst, E, Nb);
    scan_kernel<<<1, 1024>>>(NBLK * N);
    build_kernel<<<(E + 255) / 256, 256>>>(src, dst, ea, x, E, Nb);

    // ---- layer 0 ----
    l0_kernel<<<nodeBlocks, 256>>>(x, W0, root0, b0, N);

    // ---- layer 1 ----
    transform_kernel<<<tGrid, 256>>>(hP, W1, root1, N);
    for (int p = 0; p < NBLK; p++)
        node_pass_kernel<<<nodeBlocks, 256>>>(b1, hP, N, p, p == NBLK - 1);

    // ---- layer 2 ----
    transform_kernel<<<tGrid, 256>>>(hP, W2, root2, N);
    for (int p = 0; p < NBLK; p++)
        node_pass_kernel<<<nodeBlocks, 256>>>(b2, out, N, p, p == NBLK - 1);
}